// round 7
// baseline (speedup 1.0000x reference)
#include <cuda_runtime.h>
#include <math.h>
#include <stdint.h>

#define B_ 4
#define N_ 2048
#define D_ 1024
#define E_ 8
#define BT_ 128
#define PAIRS (B_*E_)
#define TOK (B_*N_)

// ---------------- scratch (static __device__ globals; no allocs) ----------------
__device__ float g_h  [(size_t)PAIRS*N_*BT_];
__device__ float g_qb [(size_t)PAIRS*N_*BT_];
__device__ float g_kb [(size_t)PAIRS*N_*BT_];
__device__ float g_vb [(size_t)PAIRS*N_*BT_];
__device__ float g_ya [(size_t)PAIRS*N_*BT_];
__device__ float g_yup[(size_t)PAIRS*N_*D_];
__device__ int   g_idx[PAIRS*N_];
__device__ int   g_cnt[PAIRS];
__device__ int   g_top2[TOK*2];
__device__ float g_topw[TOK*2];
__device__ float g_probs[TOK*E_];
__device__ int   g_prow[TOK*2];

// ---------------- 1. router ----------------
__global__ void router_kernel(const float* __restrict__ x, const float* __restrict__ Wg){
    int tok = blockIdx.x;
    int tid = threadIdx.x;
    float a[E_];
    #pragma unroll
    for(int e=0;e<E_;e++) a[e]=0.f;
    const float* xr = x + (size_t)tok*D_;
    for(int d=tid; d<D_; d+=256){
        float xv = xr[d];
        const float* wg = Wg + d*E_;
        #pragma unroll
        for(int e=0;e<E_;e++) a[e] += xv*wg[e];
    }
    #pragma unroll
    for(int e=0;e<E_;e++)
        for(int off=16;off>0;off>>=1) a[e] += __shfl_down_sync(0xffffffffu,a[e],off);
    __shared__ float sm[8][E_];
    __shared__ float lg[E_];
    int w = tid>>5;
    if((tid&31)==0){ for(int e=0;e<E_;e++) sm[w][e]=a[e]; }
    __syncthreads();
    if(tid<E_){ float s=0.f; for(int w2=0;w2<8;w2++) s+=sm[w2][tid]; lg[tid]=s; }
    __syncthreads();
    if(tid==0){
        float mx=lg[0];
        #pragma unroll
        for(int e=1;e<E_;e++) mx=fmaxf(mx,lg[e]);
        float p[E_]; float s=0.f;
        #pragma unroll
        for(int e=0;e<E_;e++){ p[e]=__expf(lg[e]-mx); s+=p[e]; }
        float inv=1.f/s;
        #pragma unroll
        for(int e=0;e<E_;e++){ p[e]*=inv; g_probs[tok*E_+e]=p[e]; }
        int i0=0;
        #pragma unroll
        for(int e=1;e<E_;e++) if(p[e]>p[i0]) i0=e;
        int i1=(i0==0)?1:0;
        #pragma unroll
        for(int e=0;e<E_;e++){ if(e==i0) continue; if(p[e]>p[i1]) i1=e; }
        float ws=p[i0]+p[i1];
        g_top2[tok*2]=i0;  g_top2[tok*2+1]=i1;
        g_topw[tok*2]=p[i0]/ws; g_topw[tok*2+1]=p[i1]/ws;
        g_prow[tok*2]=-1;  g_prow[tok*2+1]=-1;
    }
}

// ---------------- 2. ordered compaction per (b,e) ----------------
__global__ void compact_kernel(const int* __restrict__ act){
    int pair=blockIdx.x; int b=pair>>3, e=pair&7;
    int tid=threadIdx.x, w=tid>>5, lane=tid&31;
    __shared__ int wcnt[8], woff[8], sbase;
    if(tid==0) sbase=0;
    __syncthreads();
    for(int c0=0;c0<N_;c0+=256){
        int n=c0+tid;
        int tok=b*N_+n;
        int i0=g_top2[tok*2], i1=g_top2[tok*2+1];
        int pred = (act[tok]!=0) && (i0==e || i1==e);
        unsigned bal=__ballot_sync(0xffffffffu,(unsigned)pred);
        int pre=__popc(bal & ((1u<<lane)-1u));
        if(lane==0) wcnt[w]=__popc(bal);
        __syncthreads();
        if(tid==0){
            int run=sbase;
            for(int w2=0;w2<8;w2++){ woff[w2]=run; run+=wcnt[w2]; }
            sbase=run;
        }
        __syncthreads();
        if(pred){
            int pos=woff[w]+pre;
            g_idx[pair*N_+pos]=n;
            int slot=(i0==e)?0:1;
            g_prow[tok*2+slot]=pair*N_+pos;
        }
        __syncthreads();
    }
    if(tid==0) g_cnt[pair]=sbase;
}

// ============================================================================
// tf32 3x-compensated tensor-core GEMM core
// Block tile 128x128, 256 thr = 8 warps (4x2), warp tile m32 x n64,
// mma.sync.m16n8k8 tf32; D += Ahi*Bhi + Ahi*Blo + Alo*Bhi (fp32-accurate)
// ============================================================================

__device__ __forceinline__ uint32_t f2tf(float f){
    uint32_t r;
    asm("cvt.rna.tf32.f32 %0, %1;" : "=r"(r) : "f"(f));
    return r;
}
__device__ __forceinline__ void split_tf(float v, uint32_t& hi, uint32_t& lo){
    hi = f2tf(v);
    lo = f2tf(v - __uint_as_float(hi));
}
__device__ __forceinline__ void mma_tf32(float* c, const uint32_t* a, const uint32_t* b){
    asm volatile(
        "mma.sync.aligned.m16n8k8.row.col.f32.tf32.tf32.f32 "
        "{%0,%1,%2,%3}, {%4,%5,%6,%7}, {%8,%9}, {%0,%1,%2,%3};"
        : "+f"(c[0]),"+f"(c[1]),"+f"(c[2]),"+f"(c[3])
        : "r"(a[0]),"r"(a[1]),"r"(a[2]),"r"(a[3]), "r"(b[0]),"r"(b[1]));
}

// As: [128][20] pad, Bs: [16][136] pad (both conflict-free for frag reads)
__device__ __forceinline__ void gemm_tf32(const float* const* rowptr,
        const float* __restrict__ Bp, int bstride, int ktot,
        float* __restrict__ Cdst, int cstride, int rb, int cnt, int cbase,
        float* As, float* Bs)
{
    int tid=threadIdx.x;
    int lane=tid&31, w=tid>>5;
    int wm=w&3, wn=w>>2;
    int gid=lane>>2, tig=lane&3;
    float c[2][8][4];
    #pragma unroll
    for(int mt=0;mt<2;mt++){
        #pragma unroll
        for(int nt=0;nt<8;nt++){
            #pragma unroll
            for(int i=0;i<4;i++) c[mt][nt][i]=0.f;
        }
    }
    for(int k0=0;k0<ktot;k0+=16){
        __syncthreads();
        #pragma unroll
        for(int s=0;s<2;s++){
            int j=tid+s*256; int row=j>>2, c4=j&3;
            *(float4*)(As+row*20+c4*4) = *(const float4*)(rowptr[row]+k0+c4*4);
        }
        #pragma unroll
        for(int s=0;s<2;s++){
            int j=tid+s*256; int kk=j>>5, c4=j&31;
            *(float4*)(Bs+kk*136+c4*4) = *(const float4*)(Bp+(size_t)(k0+kk)*bstride+c4*4);
        }
        __syncthreads();
        #pragma unroll
        for(int s=0;s<2;s++){
            int kl=s*8;
            uint32_t ahi[2][4], alo[2][4];
            #pragma unroll
            for(int mt=0;mt<2;mt++){
                int rbase=wm*32+mt*16;
                split_tf(As[(rbase+gid  )*20+kl+tig  ], ahi[mt][0], alo[mt][0]);
                split_tf(As[(rbase+gid+8)*20+kl+tig  ], ahi[mt][1], alo[mt][1]);
                split_tf(As[(rbase+gid  )*20+kl+tig+4], ahi[mt][2], alo[mt][2]);
                split_tf(As[(rbase+gid+8)*20+kl+tig+4], ahi[mt][3], alo[mt][3]);
            }
            uint32_t bhi[8][2], blo[8][2];
            #pragma unroll
            for(int nt=0;nt<8;nt++){
                int col=wn*64+nt*8+gid;
                split_tf(Bs[(kl+tig  )*136+col], bhi[nt][0], blo[nt][0]);
                split_tf(Bs[(kl+tig+4)*136+col], bhi[nt][1], blo[nt][1]);
            }
            #pragma unroll
            for(int mt=0;mt<2;mt++){
                #pragma unroll
                for(int nt=0;nt<8;nt++){
                    mma_tf32(c[mt][nt], ahi[mt], bhi[nt]);
                    mma_tf32(c[mt][nt], ahi[mt], blo[nt]);
                    mma_tf32(c[mt][nt], alo[mt], bhi[nt]);
                }
            }
        }
    }
    #pragma unroll
    for(int mt=0;mt<2;mt++){
        #pragma unroll
        for(int nt=0;nt<8;nt++){
            int col=cbase+wn*64+nt*8+tig*2;
            int r0=rb+wm*32+mt*16+gid;
            if(r0<cnt){
                float2 v0={c[mt][nt][0],c[mt][nt][1]};
                *(float2*)(Cdst+(size_t)r0*cstride+col)=v0;
            }
            int r1=r0+8;
            if(r1<cnt){
                float2 v1={c[mt][nt][2],c[mt][nt][3]};
                *(float2*)(Cdst+(size_t)r1*cstride+col)=v1;
            }
        }
    }
}

// ---------------- 3. down-proj: gathered x @ W_down[e]  (K=1024, N=128) ----------------
__global__ __launch_bounds__(256) void down_kernel(const float* __restrict__ x,
                                                   const float* __restrict__ Wd){
    __shared__ float As[128*20];
    __shared__ float Bs[16*136];
    __shared__ const float* rowptr[128];
    int pair=blockIdx.x;
    int cnt=g_cnt[pair];
    int rb=blockIdx.y*128;
    if(rb>=cnt) return;
    int b=pair>>3, e=pair&7;
    const int* idx=g_idx+pair*N_;
    if(threadIdx.x<128){
        int rr=rb+threadIdx.x; if(rr>=cnt) rr=cnt-1;
        rowptr[threadIdx.x]=x+((size_t)(b*N_+idx[rr]))*D_;
    }
    __syncthreads();
    gemm_tf32(rowptr, Wd+(size_t)e*D_*BT_, BT_, D_,
              g_h+(size_t)pair*N_*BT_, BT_, rb, cnt, 0, As, Bs);
}

// ---------------- 4. q/k/v merged: h @ {Wq,Wk,Wv}  (K=128, N=128) ----------------
__global__ __launch_bounds__(256) void qkv_kernel(const float* __restrict__ Wq,
                                                  const float* __restrict__ Wk,
                                                  const float* __restrict__ Wv){
    __shared__ float As[128*20];
    __shared__ float Bs[16*136];
    __shared__ const float* rowptr[128];
    int pair=blockIdx.x;
    int cnt=g_cnt[pair];
    int rb=blockIdx.y*128;
    if(rb>=cnt) return;
    int e=pair&7;
    const float* A=g_h+(size_t)pair*N_*BT_;
    if(threadIdx.x<128){
        int rr=rb+threadIdx.x; if(rr>=cnt) rr=cnt-1;
        rowptr[threadIdx.x]=A+(size_t)rr*BT_;
    }
    __syncthreads();
    gemm_tf32(rowptr, Wq+(size_t)e*BT_*BT_, BT_, BT_,
              g_qb+(size_t)pair*N_*BT_, BT_, rb, cnt, 0, As, Bs);
    gemm_tf32(rowptr, Wk+(size_t)e*BT_*BT_, BT_, BT_,
              g_kb+(size_t)pair*N_*BT_, BT_, rb, cnt, 0, As, Bs);
    gemm_tf32(rowptr, Wv+(size_t)e*BT_*BT_, BT_, BT_,
              g_vb+(size_t)pair*N_*BT_, BT_, rb, cnt, 0, As, Bs);
}

// ---------------- 5. attention: 32 q/block, warp owns 4 queries, shuffle softmax ----------------
#define ATTN_SMEM ((128*128 + 128*132 + 128*36 + 32*132)*4)
__global__ __launch_bounds__(256) void attn_kernel(){
    extern __shared__ float sm[];
    float* Kt=sm;
    float* Vs=Kt+128*128;
    float* Qt=Vs+128*132;
    float* Ps=Qt+128*36;
    int pair=blockIdx.x;
    int cnt=g_cnt[pair];
    int q0=blockIdx.y*32;
    if(q0>=cnt) return;
    int t=threadIdx.x, lane=t&31, wy=t>>5;
    size_t base=(size_t)pair*N_;
    const float scale=0.08838834764831845f;
    #pragma unroll
    for(int s=0;s<4;s++){
        int j=t+s*256; int q=j>>5, dg=j&31;
        int r=q0+q; if(r>=cnt) r=cnt-1;
        float4 v=*(const float4*)(g_qb+(base+r)*BT_+dg*4);
        Qt[(dg*4+0)*36+q]=v.x*scale;
        Qt[(dg*4+1)*36+q]=v.y*scale;
        Qt[(dg*4+2)*36+q]=v.z*scale;
        Qt[(dg*4+3)*36+q]=v.w*scale;
    }
    float m[4],l[4],acc[4][4];
    #pragma unroll
    for(int i=0;i<4;i++){
        m[i]=-1e30f; l[i]=0.f;
        #pragma unroll
        for(int j=0;j<4;j++) acc[i][j]=0.f;
    }
    int iqmax=min(q0+31,cnt-1);
    for(int kb=0;kb<=iqmax;kb+=128){
        __syncthreads();
        #pragma unroll
        for(int s=0;s<16;s++){
            int j=t+s*256; int key=j>>5, dg=j&31;
            int kg=kb+key;
            float4 kv4,vv4;
            if(kg<cnt){
                kv4=*(const float4*)(g_kb+(base+kg)*BT_+dg*4);
                vv4=*(const float4*)(g_vb+(base+kg)*BT_+dg*4);
            } else {
                kv4=make_float4(0.f,0.f,0.f,0.f); vv4=kv4;
            }
            *(float4*)(&Vs[key*132+dg*4])=vv4;
            int col=key^(4*dg);
            Kt[(dg*4+0)*128+col]=kv4.x;
            Kt[(dg*4+1)*128+col]=kv4.y;
            Kt[(dg*4+2)*128+col]=kv4.z;
            Kt[(dg*4+3)*128+col]=kv4.w;
        }
        __syncthreads();
        float s4[4][4];
        #pragma unroll
        for(int i=0;i<4;i++){
            #pragma unroll
            for(int j=0;j<4;j++) s4[i][j]=0.f;
        }
        #pragma unroll 4
        for(int d=0;d<128;d++){
            float4 qv=*(const float4*)(&Qt[d*36+wy*4]);
            float4 kv=*(const float4*)(&Kt[d*128+4*(lane^(d>>2))]);
            s4[0][0]+=qv.x*kv.x; s4[0][1]+=qv.x*kv.y; s4[0][2]+=qv.x*kv.z; s4[0][3]+=qv.x*kv.w;
            s4[1][0]+=qv.y*kv.x; s4[1][1]+=qv.y*kv.y; s4[1][2]+=qv.y*kv.z; s4[1][3]+=qv.y*kv.w;
            s4[2][0]+=qv.z*kv.x; s4[2][1]+=qv.z*kv.y; s4[2][2]+=qv.z*kv.z; s4[2][3]+=qv.z*kv.w;
            s4[3][0]+=qv.w*kv.x; s4[3][1]+=qv.w*kv.y; s4[3][2]+=qv.w*kv.z; s4[3][3]+=qv.w*kv.w;
        }
        #pragma unroll
        for(int i=0;i<4;i++){
            int iq=q0+wy*4+i;
            float p[4]; float tm=-1e30f;
            #pragma unroll
            for(int j=0;j<4;j++){
                int kg=kb+lane*4+j;
                bool valid=(kg<=iq)&&(kg<cnt)&&(iq<cnt);
                p[j]=valid?s4[i][j]:-1e30f;
                tm=fmaxf(tm,p[j]);
            }
            #pragma unroll
            for(int off=16;off>0;off>>=1) tm=fmaxf(tm,__shfl_xor_sync(0xffffffffu,tm,off));
            float mn=fmaxf(m[i],tm);
            float ps=0.f;
            #pragma unroll
            for(int j=0;j<4;j++){
                int kg=kb+lane*4+j;
                bool valid=(kg<=iq)&&(kg<cnt)&&(iq<cnt);
                p[j]=valid?__expf(p[j]-mn):0.f;
                ps+=p[j];
            }
            #pragma unroll
            for(int off=16;off>0;off>>=1) ps+=__shfl_xor_sync(0xffffffffu,ps,off);
            float corr=__expf(m[i]-mn);
            l[i]=l[i]*corr+ps;
            m[i]=mn;
            #pragma unroll
            for(int j=0;j<4;j++) acc[i][j]*=corr;
            float4 pv={p[0],p[1],p[2],p[3]};
            *(float4*)(&Ps[(wy*4+i)*132+lane*4])=pv;
        }
        __syncwarp();
        #pragma unroll 4
        for(int key=0;key<128;key++){
            float4 vv=*(const float4*)(&Vs[key*132+lane*4]);
            float p0=Ps[(wy*4+0)*132+key];
            float p1=Ps[(wy*4+1)*132+key];
            float p2=Ps[(wy*4+2)*132+key];
            float p3=Ps[(wy*4+3)*132+key];
            acc[0][0]+=p0*vv.x; acc[0][1]+=p0*vv.y; acc[0][2]+=p0*vv.z; acc[0][3]+=p0*vv.w;
            acc[1][0]+=p1*vv.x; acc[1][1]+=p1*vv.y; acc[1][2]+=p1*vv.z; acc[1][3]+=p1*vv.w;
            acc[2][0]+=p2*vv.x; acc[2][1]+=p2*vv.y; acc[2][2]+=p2*vv.z; acc[2][3]+=p2*vv.w;
            acc[3][0]+=p3*vv.x; acc[3][1]+=p3*vv.y; acc[3][2]+=p3*vv.z; acc[3][3]+=p3*vv.w;
        }
        __syncwarp();
    }
    #pragma unroll
    for(int i=0;i<4;i++){
        int iq=q0+wy*4+i;
        if(iq<cnt){
            float inv=1.f/l[i];
            float4 o={acc[i][0]*inv,acc[i][1]*inv,acc[i][2]*inv,acc[i][3]*inv};
            *(float4*)(&g_ya[(base+iq)*BT_+lane*4])=o;
        }
    }
}

// ---------------- 6. up-proj: y_attn @ W_up[e]  (K=128, N=1024 tiled by 128) ----------------
__global__ __launch_bounds__(256) void up_kernel(const float* __restrict__ Wu){
    __shared__ float As[128*20];
    __shared__ float Bs[16*136];
    __shared__ const float* rowptr[128];
    int pair=blockIdx.x;
    int cnt=g_cnt[pair];
    int rb=blockIdx.y*128;
    if(rb>=cnt) return;
    int e=pair&7;
    int c0=blockIdx.z*128;
    const float* A=g_ya+(size_t)pair*N_*BT_;
    if(threadIdx.x<128){
        int rr=rb+threadIdx.x; if(rr>=cnt) rr=cnt-1;
        rowptr[threadIdx.x]=A+(size_t)rr*BT_;
    }
    __syncthreads();
    gemm_tf32(rowptr, Wu+(size_t)e*BT_*D_+c0, D_, BT_,
              g_yup+(size_t)pair*N_*D_, D_, rb, cnt, c0, As, Bs);
}

// ---------------- 7. combine (float4) ----------------
__global__ void combine_kernel(float* __restrict__ out){
    int tok=blockIdx.x;
    int r0=g_prow[tok*2], r1=g_prow[tok*2+1];
    float w0=g_topw[tok*2], w1=g_topw[tok*2+1];
    int d4=threadIdx.x;
    float4 a={0.f,0.f,0.f,0.f};
    if(r0>=0){
        float4 y=*(const float4*)(&g_yup[(size_t)r0*D_+d4*4]);
        a.x+=w0*y.x; a.y+=w0*y.y; a.z+=w0*y.z; a.w+=w0*y.w;
    }
    if(r1>=0){
        float4 y=*(const float4*)(&g_yup[(size_t)r1*D_+d4*4]);
        a.x+=w1*y.x; a.y+=w1*y.y; a.z+=w1*y.z; a.w+=w1*y.w;
    }
    *(float4*)(&out[(size_t)tok*D_+d4*4])=a;
}

// ---------------- 8. loss + max_vio ----------------
__global__ void loss_kernel(const int* __restrict__ act, float* __restrict__ out,
                            int out_size){
    int tid=threadIdx.x;
    float pm[E_];
    #pragma unroll
    for(int e=0;e<E_;e++) pm[e]=0.f;
    float asum=0.f;
    for(int t=tid;t<TOK;t+=256){
        float av=(act[t]!=0)?1.f:0.f;
        asum+=av;
        #pragma unroll
        for(int e=0;e<E_;e++) pm[e]+=g_probs[t*E_+e]*av;
    }
    __shared__ float buf[256];
    __shared__ float res[E_+1];
    for(int q=0;q<E_+1;q++){
        buf[tid]=(q<E_)?pm[q]:asum;
        __syncthreads();
        for(int s=128;s>0;s>>=1){ if(tid<s) buf[tid]+=buf[tid+s]; __syncthreads(); }
        if(tid==0) res[q]=buf[0];
        __syncthreads();
    }
    if(tid==0){
        const int topk=2;
        float denom=fmaxf(res[E_],1.f);
        float loss=0.f, mx=0.f;
        for(int e=0;e<E_;e++){
            int c=0;
            for(int b=0;b<B_;b++) c+=g_cnt[b*E_+e];
            float frac=(float)c/denom;
            loss+=frac*(res[e]/denom);
            if(frac>mx) mx=frac;
        }
        loss*=(float)E_/(float)topk;
        float vio=mx/((float)topk/(float)E_)-1.f;
        if(out_size>(int)((size_t)B_*N_*D_))   out[(size_t)B_*N_*D_]=loss;
        if(out_size>(int)((size_t)B_*N_*D_+1)) out[(size_t)B_*N_*D_+1]=vio;
    }
}

// ---------------- launch ----------------
extern "C" void kernel_launch(void* const* d_in, const int* in_sizes, int n_in,
                              void* d_out, int out_size){
    const float* x   =(const float*)d_in[0];
    const int*   pos =(const int*)d_in[1];           (void)pos;
    const int*   act =(const int*)d_in[2];
    const float* Wg  =(const float*)d_in[3];
    const float* Wd  =(const float*)d_in[4];
    const float* Wq  =(const float*)d_in[5];
    const float* Wk  =(const float*)d_in[6];
    const float* Wv  =(const float*)d_in[7];
    const float* Wu  =(const float*)d_in[8];
    (void)in_sizes; (void)n_in;
    float* out=(float*)d_out;

    cudaFuncSetAttribute(attn_kernel, cudaFuncAttributeMaxDynamicSharedMemorySize, ATTN_SMEM);

    router_kernel <<<TOK, 256>>>(x, Wg);
    compact_kernel<<<PAIRS, 256>>>(act);
    down_kernel   <<<dim3(PAIRS, N_/128), 256>>>(x, Wd);
    qkv_kernel    <<<dim3(PAIRS, N_/128), 256>>>(Wq, Wk, Wv);
    attn_kernel   <<<dim3(PAIRS, N_/32), 256, ATTN_SMEM>>>();
    up_kernel     <<<dim3(PAIRS, N_/128, D_/128), 256>>>(Wu);
    combine_kernel<<<TOK, 256>>>(out);
    loss_kernel   <<<1, 256>>>(act, out, out_size);
}

// round 9
// speedup vs baseline: 1.0570x; 1.0570x over previous
#include <cuda_runtime.h>
#include <math.h>
#include <stdint.h>

#define B_ 4
#define N_ 2048
#define D_ 1024
#define E_ 8
#define BT_ 128
#define PAIRS (B_*E_)
#define TOK (B_*N_)

// ---------------- scratch (static __device__ globals; no allocs) ----------------
__device__ float g_h  [(size_t)PAIRS*N_*BT_];
__device__ float g_qb [(size_t)PAIRS*N_*BT_];
__device__ float g_kb [(size_t)PAIRS*N_*BT_];
__device__ float g_vb [(size_t)PAIRS*N_*BT_];
__device__ float g_ya [(size_t)PAIRS*N_*BT_];
__device__ float g_yup[(size_t)PAIRS*N_*D_];
__device__ int   g_idx[PAIRS*N_];
__device__ int   g_cnt[PAIRS];
__device__ int   g_top2[TOK*2];
__device__ float g_topw[TOK*2];
__device__ float g_probs[TOK*E_];
__device__ int   g_prow[TOK*2];

// ---------------- 1. router ----------------
__global__ void router_kernel(const float* __restrict__ x, const float* __restrict__ Wg){
    int tok = blockIdx.x;
    int tid = threadIdx.x;
    float a[E_];
    #pragma unroll
    for(int e=0;e<E_;e++) a[e]=0.f;
    const float* xr = x + (size_t)tok*D_;
    for(int d=tid; d<D_; d+=256){
        float xv = xr[d];
        const float* wg = Wg + d*E_;
        #pragma unroll
        for(int e=0;e<E_;e++) a[e] += xv*wg[e];
    }
    #pragma unroll
    for(int e=0;e<E_;e++)
        for(int off=16;off>0;off>>=1) a[e] += __shfl_down_sync(0xffffffffu,a[e],off);
    __shared__ float sm[8][E_];
    __shared__ float lg[E_];
    int w = tid>>5;
    if((tid&31)==0){ for(int e=0;e<E_;e++) sm[w][e]=a[e]; }
    __syncthreads();
    if(tid<E_){ float s=0.f; for(int w2=0;w2<8;w2++) s+=sm[w2][tid]; lg[tid]=s; }
    __syncthreads();
    if(tid==0){
        float mx=lg[0];
        #pragma unroll
        for(int e=1;e<E_;e++) mx=fmaxf(mx,lg[e]);
        float p[E_]; float s=0.f;
        #pragma unroll
        for(int e=0;e<E_;e++){ p[e]=__expf(lg[e]-mx); s+=p[e]; }
        float inv=1.f/s;
        #pragma unroll
        for(int e=0;e<E_;e++){ p[e]*=inv; g_probs[tok*E_+e]=p[e]; }
        int i0=0;
        #pragma unroll
        for(int e=1;e<E_;e++) if(p[e]>p[i0]) i0=e;
        int i1=(i0==0)?1:0;
        #pragma unroll
        for(int e=0;e<E_;e++){ if(e==i0) continue; if(p[e]>p[i1]) i1=e; }
        float ws=p[i0]+p[i1];
        g_top2[tok*2]=i0;  g_top2[tok*2+1]=i1;
        g_topw[tok*2]=p[i0]/ws; g_topw[tok*2+1]=p[i1]/ws;
        g_prow[tok*2]=-1;  g_prow[tok*2+1]=-1;
    }
}

// ---------------- 2. ordered compaction per (b,e) ----------------
__global__ void compact_kernel(const int* __restrict__ act){
    int pair=blockIdx.x; int b=pair>>3, e=pair&7;
    int tid=threadIdx.x, w=tid>>5, lane=tid&31;
    __shared__ int wcnt[8], woff[8], sbase;
    if(tid==0) sbase=0;
    __syncthreads();
    for(int c0=0;c0<N_;c0+=256){
        int n=c0+tid;
        int tok=b*N_+n;
        int i0=g_top2[tok*2], i1=g_top2[tok*2+1];
        int pred = (act[tok]!=0) && (i0==e || i1==e);
        unsigned bal=__ballot_sync(0xffffffffu,(unsigned)pred);
        int pre=__popc(bal & ((1u<<lane)-1u));
        if(lane==0) wcnt[w]=__popc(bal);
        __syncthreads();
        if(tid==0){
            int run=sbase;
            for(int w2=0;w2<8;w2++){ woff[w2]=run; run+=wcnt[w2]; }
            sbase=run;
        }
        __syncthreads();
        if(pred){
            int pos=woff[w]+pre;
            g_idx[pair*N_+pos]=n;
            int slot=(i0==e)?0:1;
            g_prow[tok*2+slot]=pair*N_+pos;
        }
        __syncthreads();
    }
    if(tid==0) g_cnt[pair]=sbase;
}

// ============================================================================
// tf32 3x-compensated tensor-core GEMM core, v2
// Block tile 64x128, 256 thr = 8 warps (2m x 4n), warp tile m32 x n32.
// hi/lo tf32 split PRE-COMPUTED into smem at staging (cvt off the MMA path).
// ============================================================================

__device__ __forceinline__ uint32_t f2tf(float f){
    uint32_t r;
    asm("cvt.rna.tf32.f32 %0, %1;" : "=r"(r) : "f"(f));
    return r;
}
__device__ __forceinline__ void split_tf(float v, uint32_t& hi, uint32_t& lo){
    hi = f2tf(v);
    lo = f2tf(v - __uint_as_float(hi));
}
__device__ __forceinline__ void mma_tf32(float* c, const uint32_t* a, const uint32_t* b){
    asm volatile(
        "mma.sync.aligned.m16n8k8.row.col.f32.tf32.tf32.f32 "
        "{%0,%1,%2,%3}, {%4,%5,%6,%7}, {%8,%9}, {%0,%1,%2,%3};"
        : "+f"(c[0]),"+f"(c[1]),"+f"(c[2]),"+f"(c[3])
        : "r"(a[0]),"r"(a[1]),"r"(a[2]),"r"(a[3]), "r"(b[0]),"r"(b[1]));
}

// smem: Ah/Al [64][20], Bh/Bl [16][136]  (uint32 tf32 values)
#define GEMM_SMEM_WORDS (2*64*20 + 2*16*136)
__device__ __forceinline__ void gemm_tf32(const float* const* rowptr,
        const float* __restrict__ Bp, int bstride, int ktot,
        float* __restrict__ Cdst, int cstride, int rb, int cnt, int cbase,
        uint32_t* smbuf)
{
    uint32_t* Ah=smbuf;
    uint32_t* Al=Ah+64*20;
    uint32_t* Bh=Al+64*20;
    uint32_t* Bl=Bh+16*136;
    int tid=threadIdx.x;
    int lane=tid&31, w=tid>>5;
    int wm=w&1, wn=w>>1;               // 2 m-warps x 4 n-warps
    int gid=lane>>2, tig=lane&3;
    float c[2][4][4];
    #pragma unroll
    for(int mt=0;mt<2;mt++){
        #pragma unroll
        for(int nt=0;nt<4;nt++){
            #pragma unroll
            for(int i=0;i<4;i++) c[mt][nt][i]=0.f;
        }
    }
    int arow=tid>>2, ac4=tid&3;        // A: 64x16 = 256 float4, 1/thread
    for(int k0=0;k0<ktot;k0+=16){
        __syncthreads();
        {
            float4 v=*(const float4*)(rowptr[arow]+k0+ac4*4);
            uint32_t h,l;
            split_tf(v.x,h,l); Ah[arow*20+ac4*4+0]=h; Al[arow*20+ac4*4+0]=l;
            split_tf(v.y,h,l); Ah[arow*20+ac4*4+1]=h; Al[arow*20+ac4*4+1]=l;
            split_tf(v.z,h,l); Ah[arow*20+ac4*4+2]=h; Al[arow*20+ac4*4+2]=l;
            split_tf(v.w,h,l); Ah[arow*20+ac4*4+3]=h; Al[arow*20+ac4*4+3]=l;
        }
        #pragma unroll
        for(int s=0;s<2;s++){
            int j=tid+s*256; int kk=j>>5, c4=j&31;
            float4 v=*(const float4*)(Bp+(size_t)(k0+kk)*bstride+c4*4);
            uint32_t h,l;
            split_tf(v.x,h,l); Bh[kk*136+c4*4+0]=h; Bl[kk*136+c4*4+0]=l;
            split_tf(v.y,h,l); Bh[kk*136+c4*4+1]=h; Bl[kk*136+c4*4+1]=l;
            split_tf(v.z,h,l); Bh[kk*136+c4*4+2]=h; Bl[kk*136+c4*4+2]=l;
            split_tf(v.w,h,l); Bh[kk*136+c4*4+3]=h; Bl[kk*136+c4*4+3]=l;
        }
        __syncthreads();
        #pragma unroll
        for(int s=0;s<2;s++){
            int kl=s*8;
            uint32_t ahi[2][4], alo[2][4];
            #pragma unroll
            for(int mt=0;mt<2;mt++){
                int rbase=wm*32+mt*16;
                int i00=(rbase+gid)*20+kl+tig, i10=(rbase+gid+8)*20+kl+tig;
                ahi[mt][0]=Ah[i00];   alo[mt][0]=Al[i00];
                ahi[mt][1]=Ah[i10];   alo[mt][1]=Al[i10];
                ahi[mt][2]=Ah[i00+4]; alo[mt][2]=Al[i00+4];
                ahi[mt][3]=Ah[i10+4]; alo[mt][3]=Al[i10+4];
            }
            uint32_t bhi[4][2], blo[4][2];
            #pragma unroll
            for(int nt=0;nt<4;nt++){
                int col=wn*32+nt*8+gid;
                int j0=(kl+tig)*136+col, j1=(kl+tig+4)*136+col;
                bhi[nt][0]=Bh[j0]; blo[nt][0]=Bl[j0];
                bhi[nt][1]=Bh[j1]; blo[nt][1]=Bl[j1];
            }
            #pragma unroll
            for(int mt=0;mt<2;mt++){
                #pragma unroll
                for(int nt=0;nt<4;nt++){
                    mma_tf32(c[mt][nt], ahi[mt], bhi[nt]);
                    mma_tf32(c[mt][nt], ahi[mt], blo[nt]);
                    mma_tf32(c[mt][nt], alo[mt], bhi[nt]);
                }
            }
        }
    }
    #pragma unroll
    for(int mt=0;mt<2;mt++){
        #pragma unroll
        for(int nt=0;nt<4;nt++){
            int col=cbase+wn*32+nt*8+tig*2;
            int r0=rb+wm*32+mt*16+gid;
            if(r0<cnt){
                float2 v0={c[mt][nt][0],c[mt][nt][1]};
                *(float2*)(Cdst+(size_t)r0*cstride+col)=v0;
            }
            int r1=r0+8;
            if(r1<cnt){
                float2 v1={c[mt][nt][2],c[mt][nt][3]};
                *(float2*)(Cdst+(size_t)r1*cstride+col)=v1;
            }
        }
    }
}

// ---------------- 3. down-proj: gathered x @ W_down[e]  (K=1024, N=128) ----------------
__global__ __launch_bounds__(256) void down_kernel(const float* __restrict__ x,
                                                   const float* __restrict__ Wd){
    __shared__ uint32_t smbuf[GEMM_SMEM_WORDS];
    __shared__ const float* rowptr[64];
    int pair=blockIdx.x;
    int cnt=g_cnt[pair];
    int rb=blockIdx.y*64;
    if(rb>=cnt) return;
    int b=pair>>3, e=pair&7;
    const int* idx=g_idx+pair*N_;
    if(threadIdx.x<64){
        int rr=rb+threadIdx.x; if(rr>=cnt) rr=cnt-1;
        rowptr[threadIdx.x]=x+((size_t)(b*N_+idx[rr]))*D_;
    }
    __syncthreads();
    gemm_tf32(rowptr, Wd+(size_t)e*D_*BT_, BT_, D_,
              g_h+(size_t)pair*N_*BT_, BT_, rb, cnt, 0, smbuf);
}

// ---------------- 4. q/k/v: h @ {Wq,Wk,Wv} (z selects), (K=128, N=128) ----------------
__global__ __launch_bounds__(256) void qkv_kernel(const float* __restrict__ Wq,
                                                  const float* __restrict__ Wk,
                                                  const float* __restrict__ Wv){
    __shared__ uint32_t smbuf[GEMM_SMEM_WORDS];
    __shared__ const float* rowptr[64];
    int pair=blockIdx.x;
    int cnt=g_cnt[pair];
    int rb=blockIdx.y*64;
    if(rb>=cnt) return;
    int e=pair&7;
    int which=blockIdx.z;
    const float* W=(which==0?Wq:(which==1?Wk:Wv))+(size_t)e*BT_*BT_;
    float* dst=(which==0?g_qb:(which==1?g_kb:g_vb));
    const float* A=g_h+(size_t)pair*N_*BT_;
    if(threadIdx.x<64){
        int rr=rb+threadIdx.x; if(rr>=cnt) rr=cnt-1;
        rowptr[threadIdx.x]=A+(size_t)rr*BT_;
    }
    __syncthreads();
    gemm_tf32(rowptr, W, BT_, BT_,
              dst+(size_t)pair*N_*BT_, BT_, rb, cnt, 0, smbuf);
}

// ---------------- 5. attention: 32 q/block, warp owns 4 queries, shuffle softmax ----------------
#define ATTN_SMEM ((128*128 + 128*132 + 128*36 + 32*132)*4)
__global__ __launch_bounds__(256) void attn_kernel(){
    extern __shared__ float sm[];
    float* Kt=sm;
    float* Vs=Kt+128*128;
    float* Qt=Vs+128*132;
    float* Ps=Qt+128*36;
    int pair=blockIdx.x;
    int cnt=g_cnt[pair];
    int q0=blockIdx.y*32;
    if(q0>=cnt) return;
    int t=threadIdx.x, lane=t&31, wy=t>>5;
    size_t base=(size_t)pair*N_;
    const float scale=0.08838834764831845f;
    #pragma unroll
    for(int s=0;s<4;s++){
        int j=t+s*256; int q=j>>5, dg=j&31;
        int r=q0+q; if(r>=cnt) r=cnt-1;
        float4 v=*(const float4*)(g_qb+(base+r)*BT_+dg*4);
        Qt[(dg*4+0)*36+q]=v.x*scale;
        Qt[(dg*4+1)*36+q]=v.y*scale;
        Qt[(dg*4+2)*36+q]=v.z*scale;
        Qt[(dg*4+3)*36+q]=v.w*scale;
    }
    float m[4],l[4],acc[4][4];
    #pragma unroll
    for(int i=0;i<4;i++){
        m[i]=-1e30f; l[i]=0.f;
        #pragma unroll
        for(int j=0;j<4;j++) acc[i][j]=0.f;
    }
    int iqmax=min(q0+31,cnt-1);
    for(int kb=0;kb<=iqmax;kb+=128){
        __syncthreads();
        #pragma unroll
        for(int s=0;s<16;s++){
            int j=t+s*256; int key=j>>5, dg=j&31;
            int kg=kb+key;
            float4 kv4,vv4;
            if(kg<cnt){
                kv4=*(const float4*)(g_kb+(base+kg)*BT_+dg*4);
                vv4=*(const float4*)(g_vb+(base+kg)*BT_+dg*4);
            } else {
                kv4=make_float4(0.f,0.f,0.f,0.f); vv4=kv4;
            }
            *(float4*)(&Vs[key*132+dg*4])=vv4;
            int col=key^(4*dg);
            Kt[(dg*4+0)*128+col]=kv4.x;
            Kt[(dg*4+1)*128+col]=kv4.y;
            Kt[(dg*4+2)*128+col]=kv4.z;
            Kt[(dg*4+3)*128+col]=kv4.w;
        }
        __syncthreads();
        float s4[4][4];
        #pragma unroll
        for(int i=0;i<4;i++){
            #pragma unroll
            for(int j=0;j<4;j++) s4[i][j]=0.f;
        }
        #pragma unroll 4
        for(int d=0;d<128;d++){
            float4 qv=*(const float4*)(&Qt[d*36+wy*4]);
            float4 kv=*(const float4*)(&Kt[d*128+4*(lane^(d>>2))]);
            s4[0][0]+=qv.x*kv.x; s4[0][1]+=qv.x*kv.y; s4[0][2]+=qv.x*kv.z; s4[0][3]+=qv.x*kv.w;
            s4[1][0]+=qv.y*kv.x; s4[1][1]+=qv.y*kv.y; s4[1][2]+=qv.y*kv.z; s4[1][3]+=qv.y*kv.w;
            s4[2][0]+=qv.z*kv.x; s4[2][1]+=qv.z*kv.y; s4[2][2]+=qv.z*kv.z; s4[2][3]+=qv.z*kv.w;
            s4[3][0]+=qv.w*kv.x; s4[3][1]+=qv.w*kv.y; s4[3][2]+=qv.w*kv.z; s4[3][3]+=qv.w*kv.w;
        }
        #pragma unroll
        for(int i=0;i<4;i++){
            int iq=q0+wy*4+i;
            float p[4]; float tm=-1e30f;
            #pragma unroll
            for(int j=0;j<4;j++){
                int kg=kb+lane*4+j;
                bool valid=(kg<=iq)&&(kg<cnt)&&(iq<cnt);
                p[j]=valid?s4[i][j]:-1e30f;
                tm=fmaxf(tm,p[j]);
            }
            #pragma unroll
            for(int off=16;off>0;off>>=1) tm=fmaxf(tm,__shfl_xor_sync(0xffffffffu,tm,off));
            float mn=fmaxf(m[i],tm);
            float ps=0.f;
            #pragma unroll
            for(int j=0;j<4;j++){
                int kg=kb+lane*4+j;
                bool valid=(kg<=iq)&&(kg<cnt)&&(iq<cnt);
                p[j]=valid?__expf(p[j]-mn):0.f;
                ps+=p[j];
            }
            #pragma unroll
            for(int off=16;off>0;off>>=1) ps+=__shfl_xor_sync(0xffffffffu,ps,off);
            float corr=__expf(m[i]-mn);
            l[i]=l[i]*corr+ps;
            m[i]=mn;
            #pragma unroll
            for(int j=0;j<4;j++) acc[i][j]*=corr;
            float4 pv={p[0],p[1],p[2],p[3]};
            *(float4*)(&Ps[(wy*4+i)*132+lane*4])=pv;
        }
        __syncwarp();
        #pragma unroll 4
        for(int key=0;key<128;key++){
            float4 vv=*(const float4*)(&Vs[key*132+lane*4]);
            float p0=Ps[(wy*4+0)*132+key];
            float p1=Ps[(wy*4+1)*132+key];
            float p2=Ps[(wy*4+2)*132+key];
            float p3=Ps[(wy*4+3)*132+key];
            acc[0][0]+=p0*vv.x; acc[0][1]+=p0*vv.y; acc[0][2]+=p0*vv.z; acc[0][3]+=p0*vv.w;
            acc[1][0]+=p1*vv.x; acc[1][1]+=p1*vv.y; acc[1][2]+=p1*vv.z; acc[1][3]+=p1*vv.w;
            acc[2][0]+=p2*vv.x; acc[2][1]+=p2*vv.y; acc[2][2]+=p2*vv.z; acc[2][3]+=p2*vv.w;
            acc[3][0]+=p3*vv.x; acc[3][1]+=p3*vv.y; acc[3][2]+=p3*vv.z; acc[3][3]+=p3*vv.w;
        }
        __syncwarp();
    }
    #pragma unroll
    for(int i=0;i<4;i++){
        int iq=q0+wy*4+i;
        if(iq<cnt){
            float inv=1.f/l[i];
            float4 o={acc[i][0]*inv,acc[i][1]*inv,acc[i][2]*inv,acc[i][3]*inv};
            *(float4*)(&g_ya[(base+iq)*BT_+lane*4])=o;
        }
    }
}

// ---------------- 6. up-proj: y_attn @ W_up[e]  (K=128, N=1024 tiled by 128) ----------------
__global__ __launch_bounds__(256) void up_kernel(const float* __restrict__ Wu){
    __shared__ uint32_t smbuf[GEMM_SMEM_WORDS];
    __shared__ const float* rowptr[64];
    int pair=blockIdx.x;
    int cnt=g_cnt[pair];
    int rb=blockIdx.y*64;
    if(rb>=cnt) return;
    int e=pair&7;
    int c0=blockIdx.z*128;
    const float* A=g_ya+(size_t)pair*N_*BT_;
    if(threadIdx.x<64){
        int rr=rb+threadIdx.x; if(rr>=cnt) rr=cnt-1;
        rowptr[threadIdx.x]=A+(size_t)rr*BT_;
    }
    __syncthreads();
    gemm_tf32(rowptr, Wu+(size_t)e*BT_*D_+c0, D_, BT_,
              g_yup+(size_t)pair*N_*D_, D_, rb, cnt, c0, smbuf);
}

// ---------------- 7. combine (float4) ----------------
__global__ void combine_kernel(float* __restrict__ out){
    int tok=blockIdx.x;
    int r0=g_prow[tok*2], r1=g_prow[tok*2+1];
    float w0=g_topw[tok*2], w1=g_topw[tok*2+1];
    int d4=threadIdx.x;
    float4 a={0.f,0.f,0.f,0.f};
    if(r0>=0){
        float4 y=*(const float4*)(&g_yup[(size_t)r0*D_+d4*4]);
        a.x+=w0*y.x; a.y+=w0*y.y; a.z+=w0*y.z; a.w+=w0*y.w;
    }
    if(r1>=0){
        float4 y=*(const float4*)(&g_yup[(size_t)r1*D_+d4*4]);
        a.x+=w1*y.x; a.y+=w1*y.y; a.z+=w1*y.z; a.w+=w1*y.w;
    }
    *(float4*)(&out[(size_t)tok*D_+d4*4])=a;
}

// ---------------- 8. loss + max_vio ----------------
__global__ void loss_kernel(const int* __restrict__ act, float* __restrict__ out,
                            int out_size){
    int tid=threadIdx.x;
    float pm[E_];
    #pragma unroll
    for(int e=0;e<E_;e++) pm[e]=0.f;
    float asum=0.f;
    for(int t=tid;t<TOK;t+=256){
        float av=(act[t]!=0)?1.f:0.f;
        asum+=av;
        #pragma unroll
        for(int e=0;e<E_;e++) pm[e]+=g_probs[t*E_+e]*av;
    }
    __shared__ float buf[256];
    __shared__ float res[E_+1];
    for(int q=0;q<E_+1;q++){
        buf[tid]=(q<E_)?pm[q]:asum;
        __syncthreads();
        for(int s=128;s>0;s>>=1){ if(tid<s) buf[tid]+=buf[tid+s]; __syncthreads(); }
        if(tid==0) res[q]=buf[0];
        __syncthreads();
    }
    if(tid==0){
        const int topk=2;
        float denom=fmaxf(res[E_],1.f);
        float loss=0.f, mx=0.f;
        for(int e=0;e<E_;e++){
            int c=0;
            for(int b=0;b<B_;b++) c+=g_cnt[b*E_+e];
            float frac=(float)c/denom;
            loss+=frac*(res[e]/denom);
            if(frac>mx) mx=frac;
        }
        loss*=(float)E_/(float)topk;
        float vio=mx/((float)topk/(float)E_)-1.f;
        if(out_size>(int)((size_t)B_*N_*D_))   out[(size_t)B_*N_*D_]=loss;
        if(out_size>(int)((size_t)B_*N_*D_+1)) out[(size_t)B_*N_*D_+1]=vio;
    }
}

// ---------------- launch ----------------
extern "C" void kernel_launch(void* const* d_in, const int* in_sizes, int n_in,
                              void* d_out, int out_size){
    const float* x   =(const float*)d_in[0];
    const int*   pos =(const int*)d_in[1];           (void)pos;
    const int*   act =(const int*)d_in[2];
    const float* Wg  =(const float*)d_in[3];
    const float* Wd  =(const float*)d_in[4];
    const float* Wq  =(const float*)d_in[5];
    const float* Wk  =(const float*)d_in[6];
    const float* Wv  =(const float*)d_in[7];
    const float* Wu  =(const float*)d_in[8];
    (void)in_sizes; (void)n_in;
    float* out=(float*)d_out;

    cudaFuncSetAttribute(attn_kernel, cudaFuncAttributeMaxDynamicSharedMemorySize, ATTN_SMEM);

    router_kernel <<<TOK, 256>>>(x, Wg);
    compact_kernel<<<PAIRS, 256>>>(act);
    down_kernel   <<<dim3(PAIRS, N_/64), 256>>>(x, Wd);
    qkv_kernel    <<<dim3(PAIRS, N_/64, 3), 256>>>(Wq, Wk, Wv);
    attn_kernel   <<<dim3(PAIRS, N_/32), 256, ATTN_SMEM>>>();
    up_kernel     <<<dim3(PAIRS, N_/64, D_/128), 256>>>(Wu);
    combine_kernel<<<TOK, 256>>>(out);
    loss_kernel   <<<1, 256>>>(act, out, out_size);
}